// round 5
// baseline (speedup 1.0000x reference)
#include <cuda_runtime.h>
#include <cuda_bf16.h>
#include <cstdint>
#include <math.h>

#define BB 4
#define TT 2048
#define CC 1024
#define HH 16
#define HD 64
#define BH (BB*HH)   /* 64 */
#define MM (BB*TT)   /* 8192 */

// ------------------------- scratch (static device globals; no allocs) ---------
__device__ __nv_bfloat16 g_xb[(size_t)MM*CC];          // x in bf16
__device__ __nv_bfloat16 g_WT[4][(size_t)CC*CC];       // Wq,Wk,Wv,Wo transposed [n][k] bf16
__device__ __nv_bfloat16 g_bias[4][CC];                // bq,bk,bv,bo bf16
__device__ __nv_bfloat16 g_q[(size_t)BH*TT*HD];        // [bh][t][d] post-rope bf16
__device__ __nv_bfloat16 g_k[(size_t)BH*TT*HD];
__device__ __nv_bfloat16 g_v[(size_t)BH*TT*HD];
__device__ __nv_bfloat16 g_S[(size_t)BH*TT*TT];        // bf16 scaled logits (lower-tri tiles)
__device__ float         g_m[BH*TT];                   // row max of scaled logits
__device__ __nv_bfloat16 g_y[(size_t)MM*CC];           // attention output bf16 [b*T+t][h*64+d]
__device__ float         g_cos[TT*(HD/2)];
__device__ float         g_sin[TT*(HD/2)];

// ------------------------- accurate f32 exp (cephes/Eigen pexp style) ---------
// Built entirely from __fmaf_rn/__fmul_rn/__fadd_rn so --use_fast_math cannot
// substitute MUFU-based approximations. ~1-2 ulp, same algorithm as Eigen pexp
// (what XLA:CPU uses), so it near-bit-matches the reference softmax exp.
__device__ __forceinline__ float exp_rn(float x) {
    x = fmaxf(x, -87.0f);
    float mf = floorf(__fmaf_rn(x, 1.44269504088896341f, 0.5f));
    float r  = __fmaf_rn(mf, -0.693359375f, x);
    r        = __fmaf_rn(mf,  2.12194440e-4f, r);
    float p  = 1.9875691500e-4f;
    p = __fmaf_rn(p, r, 1.3981999507e-3f);
    p = __fmaf_rn(p, r, 8.3334519073e-3f);
    p = __fmaf_rn(p, r, 4.1665795894e-2f);
    p = __fmaf_rn(p, r, 1.6666665459e-1f);
    p = __fmaf_rn(p, r, 5.0000001201e-1f);
    float y = __fmaf_rn(p, __fmul_rn(r, r), r);
    y = __fadd_rn(y, 1.0f);
    int mi = (int)mf;
    float sc = __int_as_float((mi + 127) << 23);
    return __fmul_rn(y, sc);
}

// ------------------------- mma.sync m16n8k16 bf16 -----------------------------
__device__ __forceinline__ void mma_bf16(float c[4], const uint32_t a[4], const uint32_t b[2]) {
    asm volatile(
        "mma.sync.aligned.m16n8k16.row.col.f32.bf16.bf16.f32 "
        "{%0,%1,%2,%3}, {%4,%5,%6,%7}, {%8,%9}, {%0,%1,%2,%3};\n"
        : "+f"(c[0]), "+f"(c[1]), "+f"(c[2]), "+f"(c[3])
        : "r"(a[0]), "r"(a[1]), "r"(a[2]), "r"(a[3]), "r"(b[0]), "r"(b[1]));
}

// ------------------------- prep kernels ---------------------------------------
__global__ void k_conv_x(const float* __restrict__ x) {
    size_t i = ((size_t)blockIdx.x * 256 + threadIdx.x) * 4;
    float4 v = *(const float4*)(x + i);
    __nv_bfloat162 a, b;
    a.x = __float2bfloat16(v.x); a.y = __float2bfloat16(v.y);
    b.x = __float2bfloat16(v.z); b.y = __float2bfloat16(v.w);
    *(__nv_bfloat162*)(g_xb + i)     = a;
    *(__nv_bfloat162*)(g_xb + i + 2) = b;
}

__global__ void k_prepW(const float* __restrict__ Wq, const float* __restrict__ Wk,
                        const float* __restrict__ Wv, const float* __restrict__ Wo) {
    const float* W = (blockIdx.z == 0) ? Wq : (blockIdx.z == 1) ? Wk : (blockIdx.z == 2) ? Wv : Wo;
    __shared__ float tile[32][33];
    int n0 = blockIdx.x * 32, k0 = blockIdx.y * 32;
    for (int jj = threadIdx.y; jj < 32; jj += 8)
        tile[jj][threadIdx.x] = W[(size_t)(k0 + jj) * CC + n0 + threadIdx.x];
    __syncthreads();
    for (int jj = threadIdx.y; jj < 32; jj += 8)
        g_WT[blockIdx.z][(size_t)(n0 + jj) * CC + k0 + threadIdx.x] =
            __float2bfloat16(tile[threadIdx.x][jj]);
}

__global__ void k_biasprep(const float* __restrict__ bq, const float* __restrict__ bk,
                           const float* __restrict__ bv, const float* __restrict__ bo) {
    const float* p = (blockIdx.x == 0) ? bq : (blockIdx.x == 1) ? bk : (blockIdx.x == 2) ? bv : bo;
    g_bias[blockIdx.x][threadIdx.x] = __float2bfloat16(p[threadIdx.x]);
}

__global__ void k_rope() {
    int t = blockIdx.x, j = threadIdx.x;                 // j in 0..31
    double e = (double)(2 * j) / 64.0;                   // exact in f32/f64
    float p32 = (float)pow(10000.0, e);                  // f32 rounding of pow (ref rounding #1)
    float inv = __fdiv_rn(1.0f, p32);                    // f32 reciprocal   (ref rounding #2)
    float ang = __fmul_rn((float)t, inv);                // f32 angle like reference
    g_cos[t * (HD/2) + j] = (float)cos((double)ang);     // ~correctly-rounded f32 cos/sin
    g_sin[t * (HD/2) + j] = (float)sin((double)ang);
}

// ------------------------- GEMM: x@W (+bias, rope) / y@Wo --------------------
// block tile 128x128, kTile 32, 256 threads, warp tile 32x64
__global__ __launch_bounds__(256) void k_gemm(int mode_base, float* __restrict__ outF)
{
    const int mode = mode_base + blockIdx.z;             // 0=q 1=k 2=v 3=out-proj
    const __nv_bfloat16* __restrict__ A  = (mode < 3) ? g_xb : g_y;
    const __nv_bfloat16* __restrict__ Bt = g_WT[mode];
    const __nv_bfloat16* __restrict__ bs = g_bias[mode];
    const int m0 = blockIdx.y * 128;
    const int n0 = blockIdx.x * 128;

    __shared__ __nv_bfloat16 sA[128 * 56];
    __shared__ __nv_bfloat16 sB[128 * 56];

    const int tid = threadIdx.x;
    const int wid = tid >> 5, lane = tid & 31;
    const int g = lane >> 2, t4 = lane & 3;
    const int wm = wid & 3, wn = wid >> 2;

    float acc[16][4];
    #pragma unroll
    for (int i = 0; i < 16; i++) { acc[i][0] = acc[i][1] = acc[i][2] = acc[i][3] = 0.f; }

    for (int k0 = 0; k0 < CC; k0 += 32) {
        #pragma unroll
        for (int rep = 0; rep < 2; rep++) {
            int i = tid + rep * 256;
            int row = i >> 2, cg = i & 3;
            *(uint4*)&sA[row * 56 + cg * 8] = *(const uint4*)(A  + (size_t)(m0 + row) * CC + k0 + cg * 8);
            *(uint4*)&sB[row * 56 + cg * 8] = *(const uint4*)(Bt + (size_t)(n0 + row) * CC + k0 + cg * 8);
        }
        __syncthreads();
        #pragma unroll
        for (int ks = 0; ks < 32; ks += 16) {
            uint32_t af[2][4];
            #pragma unroll
            for (int mt = 0; mt < 2; mt++) {
                int r = wm * 32 + mt * 16 + g;
                af[mt][0] = *(const uint32_t*)&sA[(r    ) * 56 + ks     + 2 * t4];
                af[mt][1] = *(const uint32_t*)&sA[(r + 8) * 56 + ks     + 2 * t4];
                af[mt][2] = *(const uint32_t*)&sA[(r    ) * 56 + ks + 8 + 2 * t4];
                af[mt][3] = *(const uint32_t*)&sA[(r + 8) * 56 + ks + 8 + 2 * t4];
            }
            uint32_t bfr[8][2];
            #pragma unroll
            for (int nt = 0; nt < 8; nt++) {
                int n = wn * 64 + nt * 8 + g;
                bfr[nt][0] = *(const uint32_t*)&sB[n * 56 + ks     + 2 * t4];
                bfr[nt][1] = *(const uint32_t*)&sB[n * 56 + ks + 8 + 2 * t4];
            }
            #pragma unroll
            for (int mt = 0; mt < 2; mt++)
                #pragma unroll
                for (int nt = 0; nt < 8; nt++)
                    mma_bf16(acc[mt * 8 + nt], af[mt], bfr[nt]);
        }
        __syncthreads();
    }

    // epilogue
    #pragma unroll
    for (int mt = 0; mt < 2; mt++) {
        #pragma unroll
        for (int nt = 0; nt < 8; nt++) {
            float* c = acc[mt * 8 + nt];
            int col = n0 + wn * 64 + nt * 8 + 2 * t4;       // even
            int r0  = m0 + wm * 32 + mt * 16 + g;
            #pragma unroll
            for (int hf = 0; hf < 2; hf++) {
                int row = r0 + hf * 8;
                __nv_bfloat16 eb = __hadd(__float2bfloat16(c[hf * 2 + 0]), bs[col]);
                __nv_bfloat16 ob = __hadd(__float2bfloat16(c[hf * 2 + 1]), bs[col + 1]);
                if (mode == 3) {
                    outF[(size_t)row * CC + col]     = __bfloat162float(eb);
                    outF[(size_t)row * CC + col + 1] = __bfloat162float(ob);
                } else {
                    int b = row >> 11, t = row & (TT - 1);
                    int h = col >> 6,  d = col & 63;
                    size_t oidx = ((size_t)(b * HH + h) * TT + t) * HD + d;
                    __nv_bfloat162 pr;
                    if (mode <= 1) {                         // rope for q,k
                        int j = d >> 1;
                        float cth = g_cos[t * (HD/2) + j], sth = g_sin[t * (HD/2) + j];
                        float ef = __bfloat162float(eb), of = __bfloat162float(ob);
                        // mul/mul/sub(add) exactly like eager XLA: no FMA contraction
                        float re = __fsub_rn(__fmul_rn(ef, cth), __fmul_rn(of, sth));
                        float ro = __fadd_rn(__fmul_rn(ef, sth), __fmul_rn(of, cth));
                        pr.x = __float2bfloat16(re);
                        pr.y = __float2bfloat16(ro);
                    } else {
                        pr.x = eb; pr.y = ob;
                    }
                    __nv_bfloat16* outp = (mode == 0) ? g_q : (mode == 1) ? g_k : g_v;
                    *(__nv_bfloat162*)(outp + oidx) = pr;
                }
            }
        }
    }
}

// ------------------------- attention pass A: S = bf16(QK^T)*0.125, row max ----
__global__ __launch_bounds__(256) void k_attA()
{
    const int qt = blockIdx.x, bh = blockIdx.y;
    const int q0 = qt * 64;
    const __nv_bfloat16* __restrict__ Q = g_q + (size_t)bh * TT * HD;
    const __nv_bfloat16* __restrict__ K = g_k + (size_t)bh * TT * HD;
    __shared__ __nv_bfloat16 sQ[64 * 72];
    __shared__ __nv_bfloat16 sK[64 * 72];
    __shared__ float sMax[2][64];

    const int tid = threadIdx.x;
    const int wid = tid >> 5, lane = tid & 31;
    const int g = lane >> 2, t4 = lane & 3;
    const int wm = wid & 3, wn = wid >> 2;

    #pragma unroll
    for (int rep = 0; rep < 2; rep++) {
        int i = tid + rep * 256;
        int row = i >> 3, cg = i & 7;
        *(uint4*)&sQ[row * 72 + cg * 8] = *(const uint4*)(Q + (size_t)(q0 + row) * HD + cg * 8);
    }

    const int r0  = wm * 16 + g;
    const int qg0 = q0 + r0, qg1 = qg0 + 8;
    float rmax0 = -INFINITY, rmax1 = -INFINITY;

    for (int kt = 0; kt <= qt; kt++) {
        #pragma unroll
        for (int rep = 0; rep < 2; rep++) {
            int i = tid + rep * 256;
            int row = i >> 3, cg = i & 7;
            *(uint4*)&sK[row * 72 + cg * 8] = *(const uint4*)(K + (size_t)(kt * 64 + row) * HD + cg * 8);
        }
        __syncthreads();
        float acc[4][4] = {};
        #pragma unroll
        for (int ks = 0; ks < 64; ks += 16) {
            uint32_t af[4];
            af[0] = *(const uint32_t*)&sQ[(r0    ) * 72 + ks     + 2 * t4];
            af[1] = *(const uint32_t*)&sQ[(r0 + 8) * 72 + ks     + 2 * t4];
            af[2] = *(const uint32_t*)&sQ[(r0    ) * 72 + ks + 8 + 2 * t4];
            af[3] = *(const uint32_t*)&sQ[(r0 + 8) * 72 + ks + 8 + 2 * t4];
            #pragma unroll
            for (int nt = 0; nt < 4; nt++) {
                int n = wn * 32 + nt * 8 + g;
                uint32_t bf2[2];
                bf2[0] = *(const uint32_t*)&sK[n * 72 + ks     + 2 * t4];
                bf2[1] = *(const uint32_t*)&sK[n * 72 + ks + 8 + 2 * t4];
                mma_bf16(acc[nt], af, bf2);
            }
        }
        #pragma unroll
        for (int nt = 0; nt < 4; nt++) {
            int cl = wn * 32 + nt * 8 + 2 * t4;
            int kc = kt * 64 + cl;
            {
                float s0 = __fmul_rn(__bfloat162float(__float2bfloat16(acc[nt][0])), 0.125f);
                float s1 = __fmul_rn(__bfloat162float(__float2bfloat16(acc[nt][1])), 0.125f);
                if (kc     <= qg0) rmax0 = fmaxf(rmax0, s0);
                if (kc + 1 <= qg0) rmax0 = fmaxf(rmax0, s1);
                __nv_bfloat162 pr; pr.x = __float2bfloat16(s0); pr.y = __float2bfloat16(s1);
                *(__nv_bfloat162*)(g_S + (size_t)(bh * TT + qg0) * TT + kc) = pr;
            }
            {
                float s0 = __fmul_rn(__bfloat162float(__float2bfloat16(acc[nt][2])), 0.125f);
                float s1 = __fmul_rn(__bfloat162float(__float2bfloat16(acc[nt][3])), 0.125f);
                if (kc     <= qg1) rmax1 = fmaxf(rmax1, s0);
                if (kc + 1 <= qg1) rmax1 = fmaxf(rmax1, s1);
                __nv_bfloat162 pr; pr.x = __float2bfloat16(s0); pr.y = __float2bfloat16(s1);
                *(__nv_bfloat162*)(g_S + (size_t)(bh * TT + qg1) * TT + kc) = pr;
            }
        }
        __syncthreads();
    }
    rmax0 = fmaxf(rmax0, __shfl_xor_sync(0xffffffffu, rmax0, 1));
    rmax0 = fmaxf(rmax0, __shfl_xor_sync(0xffffffffu, rmax0, 2));
    rmax1 = fmaxf(rmax1, __shfl_xor_sync(0xffffffffu, rmax1, 1));
    rmax1 = fmaxf(rmax1, __shfl_xor_sync(0xffffffffu, rmax1, 2));
    if (t4 == 0) {
        sMax[wn][wm * 16 + g]     = rmax0;
        sMax[wn][wm * 16 + g + 8] = rmax1;
    }
    __syncthreads();
    if (tid < 64) g_m[bh * TT + q0 + tid] = fmaxf(sMax[0][tid], sMax[1][tid]);
}

// ------------------------- attention pass B: softmax (bf16 probs) @ V ---------
__global__ __launch_bounds__(256) void k_attB()
{
    const int qt = blockIdx.x, bh = blockIdx.y;
    const int q0 = qt * 64;
    const int tid = threadIdx.x;
    const int wid = tid >> 5, lane = tid & 31;
    const int g = lane >> 2, t4 = lane & 3;
    const int wm = wid & 3, wn = wid >> 2;

    __shared__ float sm[64], sl[64];
    __shared__ __nv_bfloat16 sP[64 * 72];
    __shared__ __nv_bfloat16 sVt[64 * 72];

    if (tid < 64) sm[tid] = g_m[bh * TT + q0 + tid];
    __syncthreads();

    const int prow = tid >> 2;
    const int pcb  = (tid & 3) * 16;
    const int qgp  = q0 + prow;
    const float mrow = sm[prow];
    const __nv_bfloat16* __restrict__ Srow = g_S + (size_t)(bh * TT + qgp) * TT;

    // pass 1: l = sum exp(s - m)  (accurate f32 exp, f32 RN adds)
    float lp = 0.f;
    for (int kt = 0; kt <= qt; kt++) {
        __nv_bfloat16 hv[16];
        *(uint4*)&hv[0] = *(const uint4*)(Srow + kt * 64 + pcb);
        *(uint4*)&hv[8] = *(const uint4*)(Srow + kt * 64 + pcb + 8);
        #pragma unroll
        for (int j = 0; j < 16; j++) {
            int col = kt * 64 + pcb + j;
            if (col <= qgp)
                lp = __fadd_rn(lp, exp_rn(__fsub_rn(__bfloat162float(hv[j]), mrow)));
        }
    }
    lp = __fadd_rn(lp, __shfl_xor_sync(0xffffffffu, lp, 1));
    lp = __fadd_rn(lp, __shfl_xor_sync(0xffffffffu, lp, 2));
    if ((tid & 3) == 0) sl[prow] = lp;
    __syncthreads();
    const float lrow = sl[prow];

    float acc[4][4] = {};
    const int r0 = wm * 16 + g;

    for (int kt = 0; kt <= qt; kt++) {
        // probabilities, bf16-rounded like the reference (exp then IEEE-RN divide)
        {
            __nv_bfloat16 hv[16];
            *(uint4*)&hv[0] = *(const uint4*)(Srow + kt * 64 + pcb);
            *(uint4*)&hv[8] = *(const uint4*)(Srow + kt * 64 + pcb + 8);
            #pragma unroll
            for (int j = 0; j < 16; j += 2) {
                int col = kt * 64 + pcb + j;
                __nv_bfloat162 pr;
                pr.x = (col     <= qgp)
                     ? __float2bfloat16(__fdiv_rn(exp_rn(__fsub_rn(__bfloat162float(hv[j]),     mrow)), lrow))
                     : __float2bfloat16(0.f);
                pr.y = (col + 1 <= qgp)
                     ? __float2bfloat16(__fdiv_rn(exp_rn(__fsub_rn(__bfloat162float(hv[j + 1]), mrow)), lrow))
                     : __float2bfloat16(0.f);
                *(__nv_bfloat162*)&sP[prow * 72 + pcb + j] = pr;
            }
        }
        // V tile, transposed into [d][key]
        #pragma unroll
        for (int rep = 0; rep < 2; rep++) {
            int i = tid + rep * 256;
            int vr = i >> 3, d0 = (i & 7) * 8;
            __nv_bfloat16 hv[8];
            *(uint4*)&hv[0] = *(const uint4*)(g_v + (size_t)(bh * TT + kt * 64 + vr) * HD + d0);
            #pragma unroll
            for (int j = 0; j < 8; j++) sVt[(d0 + j) * 72 + vr] = hv[j];
        }
        __syncthreads();
        #pragma unroll
        for (int ks = 0; ks < 64; ks += 16) {
            uint32_t af[4];
            af[0] = *(const uint32_t*)&sP[(r0    ) * 72 + ks     + 2 * t4];
            af[1] = *(const uint32_t*)&sP[(r0 + 8) * 72 + ks     + 2 * t4];
            af[2] = *(const uint32_t*)&sP[(r0    ) * 72 + ks + 8 + 2 * t4];
            af[3] = *(const uint32_t*)&sP[(r0 + 8) * 72 + ks + 8 + 2 * t4];
            #pragma unroll
            for (int nt = 0; nt < 4; nt++) {
                int n = wn * 32 + nt * 8 + g;
                uint32_t bf2[2];
                bf2[0] = *(const uint32_t*)&sVt[n * 72 + ks     + 2 * t4];
                bf2[1] = *(const uint32_t*)&sVt[n * 72 + ks + 8 + 2 * t4];
                mma_bf16(acc[nt], af, bf2);
            }
        }
        __syncthreads();
    }

    const int b = bh >> 4, h = bh & 15;
    #pragma unroll
    for (int nt = 0; nt < 4; nt++) {
        int dcol = wn * 32 + nt * 8 + 2 * t4;
        #pragma unroll
        for (int hf = 0; hf < 2; hf++) {
            int trow = q0 + r0 + hf * 8;
            __nv_bfloat162 pr;
            pr.x = __float2bfloat16(acc[nt][hf * 2 + 0]);
            pr.y = __float2bfloat16(acc[nt][hf * 2 + 1]);
            *(__nv_bfloat162*)(g_y + (size_t)(b * TT + trow) * CC + h * HD + dcol) = pr;
        }
    }
}

// ------------------------- launch ---------------------------------------------
extern "C" void kernel_launch(void* const* d_in, const int* in_sizes, int n_in,
                              void* d_out, int out_size)
{
    (void)in_sizes; (void)n_in; (void)out_size;
    const float* x  = (const float*)d_in[0];
    const float* Wq = (const float*)d_in[1];
    const float* bq = (const float*)d_in[2];
    const float* Wk = (const float*)d_in[3];
    const float* bk = (const float*)d_in[4];
    const float* Wv = (const float*)d_in[5];
    const float* bv = (const float*)d_in[6];
    const float* Wo = (const float*)d_in[7];
    const float* bo = (const float*)d_in[8];
    float* out = (float*)d_out;

    k_conv_x  <<<(size_t)MM * CC / 1024, 256>>>(x);
    k_prepW   <<<dim3(32, 32, 4), dim3(32, 8)>>>(Wq, Wk, Wv, Wo);
    k_biasprep<<<4, 1024>>>(bq, bk, bv, bo);
    k_rope    <<<TT, 32>>>();
    k_gemm    <<<dim3(8, 64, 3), 256>>>(0, nullptr);   // q,k,v projections (+rope)
    k_attA    <<<dim3(32, 64), 256>>>();               // logits + row max
    k_attB    <<<dim3(32, 64), 256>>>();               // softmax (bf16 probs) @ V
    k_gemm    <<<dim3(8, 64, 1), 256>>>(3, out);       // output projection
}